// round 15
// baseline (speedup 1.0000x reference)
#include <cuda_runtime.h>
#include <cuda_fp16.h>
#include <cstdint>

#define Nn   20000
#define Ee   320000
#define Kk   16
#define FEATD 64
#define SEGS 4
#define SEGSZ (Nn / SEGS)        // 5000
#define NLISTS (SEGS * 2)        // 8 per query (2 halves per segment)
#define NOUT 80000
#define QTILE 128
#define CTILE 64
#define NQBLK ((Nn + QTILE - 1) / QTILE)       // 157
#define NTILES ((SEGSZ + CTILE - 1) / CTILE)   // 79
#define INFF __int_as_float(0x7F800000)

// ---------------- scratch (device globals; no allocations allowed) ----------
__device__ float g_x1[Nn * FEATD];
__device__ float g_sq[Nn];
__device__ int   g_nbr[Nn * Kk];
__device__ float g_x2[Nn * FEATD];
__device__ float g_cd[Nn * NLISTS * Kk];
__device__ int   g_ci[Nn * NLISTS * Kk];
__device__ __half g_h16[Nn * FEATD];   // fp16 hi limb
__device__ __half g_l16[Nn * FEATD];   // fp16 lo limb
__device__ float g_u[Nn * FEATD];
__device__ float g_v[Nn * FEATD];
__device__ float g_c[Nn * FEATD];
__device__ float g_d[Nn * FEATD];
__device__ float g_M[4 * 64 * 64];
__device__ float g_bb[4 * 64];

// ======================= PTX helpers (baseline, sm_80+) =====================
__device__ __forceinline__ uint32_t smem_u32(const void* p) {
    uint32_t a;
    asm("{ .reg .u64 t; cvta.to.shared.u64 t, %1; cvt.u32.u64 %0, t; }" : "=r"(a) : "l"(p));
    return a;
}
__device__ __forceinline__ void ldsm_x4(uint32_t (&r)[4], uint32_t addr) {
    asm volatile("ldmatrix.sync.aligned.m8n8.x4.shared.b16 {%0,%1,%2,%3}, [%4];"
                 : "=r"(r[0]), "=r"(r[1]), "=r"(r[2]), "=r"(r[3]) : "r"(addr));
}
__device__ __forceinline__ void mma_f16(float (&c)[4], const uint32_t (&a)[4], const uint32_t b0, const uint32_t b1) {
    asm volatile("mma.sync.aligned.m16n8k16.row.col.f32.f16.f16.f32 "
                 "{%0,%1,%2,%3}, {%4,%5,%6,%7}, {%8,%9}, {%0,%1,%2,%3};"
                 : "+f"(c[0]), "+f"(c[1]), "+f"(c[2]), "+f"(c[3])
                 : "r"(a[0]), "r"(a[1]), "r"(a[2]), "r"(a[3]), "r"(b0), "r"(b1));
}
__device__ __forceinline__ void cp_async16(uint32_t dst, const void* src, bool pred) {
    asm volatile("{\n .reg .pred p;\n setp.ne.u32 p, %0, 0;\n"
                 " @p cp.async.ca.shared.global [%1], [%2], 16;\n}"
                 :: "r"((uint32_t)pred), "r"(dst), "l"(src));
}
#define CP_COMMIT() asm volatile("cp.async.commit_group;" ::: "memory")
#define CP_WAIT1()  asm volatile("cp.async.wait_group 1;" ::: "memory")
#define CP_WAIT0()  asm volatile("cp.async.wait_group 0;" ::: "memory")
#define NBAR_SYNC(id, cnt)   asm volatile("bar.sync %0, %1;"   :: "r"(id), "r"(cnt) : "memory")
#define NBAR_ARRIVE(id, cnt) asm volatile("bar.arrive %0, %1;" :: "r"(id), "r"(cnt) : "memory")
// barrier ids: 1,2 = FULL[buf]; 3,4 = FREE[buf]; 5 = producers-only; 6 = consumers-only

// ======================= smem layout for knn (bytes) ========================
#define ROWB 144                      // 64 fp16 + 8 pad
#define A_TILE (128 * ROWB)           // 18432 per limb
#define B_TILE (64 * ROWB)            // 9216 per limb
#define SM_A   0                      // 2 limbs -> 36864
#define SM_B   36864                  // 3 ring bufs x 2 limbs x 9216 -> +55296
#define SM_S   92160                  // 2 bufs x 128 x 66 fp32 -> +67584
#define SM_SQ  159744                 // sqc[2][64] -> +512
#define SM_TOT 160256                 // 1 CTA/SM

// ======= launch 1: zero x1 + u/v precompute + tail-M precompute =============
__global__ void pre_kernel(const float* __restrict__ dep,
                           const float* __restrict__ W1a, const float* __restrict__ b1a,
                           const float* __restrict__ We,  const float* __restrict__ be,
                           const float* __restrict__ Wp,  const float* __restrict__ bp,
                           const float* __restrict__ Wr1, const float* __restrict__ br1) {
    int b = blockIdx.x, tid = threadIdx.x;
    if (b < 5000) {
        g_x1[b * 256 + tid] = 0.0f;
        return;
    }
    if (b < 7500) {
        int warp = tid >> 5, lane = tid & 31;
        int n = (b - 5000) * 8 + warp;
        float x0 = dep[3 * n], x1v = dep[3 * n + 1], x2v = dep[3 * n + 2];
        int j0 = lane, j1 = lane + 32;
        float u0 = b1a[j0] + x0 * W1a[j0] + x1v * W1a[64 + j0] + x2v * W1a[128 + j0];
        float u1 = b1a[j1] + x0 * W1a[j1] + x1v * W1a[64 + j1] + x2v * W1a[128 + j1];
        float v0 = x0 * W1a[192 + j0] + x1v * W1a[256 + j0] + x2v * W1a[320 + j0];
        float v1 = x0 * W1a[192 + j1] + x1v * W1a[256 + j1] + x2v * W1a[320 + j1];
        g_u[n * 64 + j0] = u0; g_u[n * 64 + j1] = u1;
        g_v[n * 64 + j0] = v0; g_v[n * 64 + j1] = v1;
        return;
    }
    {
        int r = b - 7500;
        __shared__ float sA[4096], sB[4096], sT[4096], sTb[64];
        for (int i = tid; i < 4096; i += 256) {
            int k = i >> 6, a = i & 63;
            sA[i] = We[k * 256 + r * 64 + a];
        }
        for (int i = tid; i < 4096; i += 256) sB[i] = Wp[i];
        __syncthreads();
        for (int i = tid; i < 4096; i += 256) {
            int k = i >> 6, bb = i & 63;
            float s = 0.0f;
            #pragma unroll 16
            for (int a = 0; a < 64; a++) s += sA[k * 64 + a] * sB[a * 64 + bb];
            sT[i] = s;
        }
        if (tid < 64) {
            float s = bp[tid];
            #pragma unroll 16
            for (int a = 0; a < 64; a++) s += be[r * 64 + a] * sB[a * 64 + tid];
            sTb[tid] = s;
        }
        __syncthreads();
        for (int i = tid; i < 4096; i += 256) sB[i] = Wr1[i];
        __syncthreads();
        for (int i = tid; i < 4096; i += 256) {
            int k = i >> 6, c = i & 63;
            float s = 0.0f;
            #pragma unroll 16
            for (int bb = 0; bb < 64; bb++) s += sT[k * 64 + bb] * sB[bb * 64 + c];
            g_M[r * 4096 + i] = s;
        }
        if (tid < 64) {
            float s = br1[tid];
            #pragma unroll 16
            for (int bb = 0; bb < 64; bb++) s += sTb[bb] * sB[bb * 64 + tid];
            g_bb[r * 64 + tid] = s;
        }
    }
}

// ======= launch 2: edge MLP (layer-1 collapsed) + segment max ===============
__global__ void edge_kernel(const int* __restrict__ eidx,
                            const float* __restrict__ W1b, const float* __restrict__ b1b) {
    __shared__ float sW1b[64 * 64];
    __shared__ float sb1b[64];
    __shared__ float hbuf[8][8][66];
    int tid = threadIdx.x;
    for (int i = tid; i < 64 * 64; i += 256) sW1b[i] = W1b[i];
    if (tid < 64) sb1b[tid] = b1b[tid];
    __syncthreads();

    int warp = tid >> 5, lane = tid & 31;
    int j0 = lane, j1 = lane + 32;
    int ebase = blockIdx.x * 64 + warp * 8;
    int* x1i = reinterpret_cast<int*>(g_x1);

    int ds[8];
    #pragma unroll
    for (int e = 0; e < 8; e++) {
        int s = eidx[ebase + e], d = eidx[Ee + ebase + e];
        ds[e] = d;
        float h0 = fmaxf(g_u[d * 64 + j0] + g_v[s * 64 + j0] - g_v[d * 64 + j0], 0.0f);
        float h1 = fmaxf(g_u[d * 64 + j1] + g_v[s * 64 + j1] - g_v[d * 64 + j1], 0.0f);
        hbuf[warp][e][j0] = h0;
        hbuf[warp][e][j1] = h1;
    }
    __syncwarp();

    float a0[8], a1[8];
    #pragma unroll
    for (int e = 0; e < 8; e++) { a0[e] = sb1b[j0]; a1[e] = sb1b[j1]; }
    #pragma unroll 8
    for (int t = 0; t < 64; t++) {
        float w0 = sW1b[t * 64 + j0], w1 = sW1b[t * 64 + j1];
        #pragma unroll
        for (int e = 0; e < 8; e++) {
            float v = hbuf[warp][e][t];
            a0[e] += v * w0;
            a1[e] += v * w1;
        }
    }
    #pragma unroll
    for (int e = 0; e < 8; e++) {
        atomicMax(&x1i[ds[e] * 64 + j0], __float_as_int(fmaxf(a0[e], 0.0f)));
        atomicMax(&x1i[ds[e] * 64 + j1], __float_as_int(fmaxf(a1[e], 0.0f)));
    }
}

// ======= launch 3: sq + fp16 2-limb split + pair c/d precompute =============
__global__ void sqcvt_kernel(const float* __restrict__ W2a, const float* __restrict__ b2a) {
    __shared__ float sW2a[128 * 64];
    __shared__ float sb2a[64];
    int tid = threadIdx.x;
    for (int i = tid; i < 128 * 64; i += 256) sW2a[i] = W2a[i];
    if (tid < 64) sb2a[tid] = b2a[tid];
    __syncthreads();

    int warp = tid >> 5, lane = tid & 31;
    int n = blockIdx.x * 8 + warp;
    int j0 = lane, j1 = lane + 32;
    float a = g_x1[n * 64 + j0];
    float b = g_x1[n * 64 + j1];

    float s = a * a + b * b;
    #pragma unroll
    for (int o = 16; o; o >>= 1) s += __shfl_xor_sync(0xFFFFFFFFu, s, o);
    if (lane == 0) g_sq[n] = s;

    {
        __half h = __float2half(a);
        g_h16[n * 64 + j0] = h;
        g_l16[n * 64 + j0] = __float2half(a - __half2float(h));
        h = __float2half(b);
        g_h16[n * 64 + j1] = h;
        g_l16[n * 64 + j1] = __float2half(b - __half2float(h));
    }

    float c0 = sb2a[j0], c1 = sb2a[j1], d0 = 0.0f, d1 = 0.0f;
    #pragma unroll 8
    for (int t = 0; t < 32; t++) {
        float xv = __shfl_sync(0xFFFFFFFFu, a, t);
        c0 += xv * sW2a[t * 64 + j0];
        c1 += xv * sW2a[t * 64 + j1];
        d0 += xv * sW2a[(64 + t) * 64 + j0];
        d1 += xv * sW2a[(64 + t) * 64 + j1];
    }
    #pragma unroll 8
    for (int t = 0; t < 32; t++) {
        float xv = __shfl_sync(0xFFFFFFFFu, b, t);
        c0 += xv * sW2a[(32 + t) * 64 + j0];
        c1 += xv * sW2a[(32 + t) * 64 + j1];
        d0 += xv * sW2a[(96 + t) * 64 + j0];
        d1 += xv * sW2a[(96 + t) * 64 + j1];
    }
    g_c[n * 64 + j0] = c0; g_c[n * 64 + j1] = c1;
    g_d[n * 64 + j0] = d0; g_d[n * 64 + j1] = d1;
}

// fully-predicated register top-16 insertion
__device__ __forceinline__ void topk_insert(float (&bd)[16], int (&bi)[16], float d, int id) {
    #pragma unroll
    for (int t = 15; t > 0; t--) {
        bool gt  = bd[t - 1] > d;
        float nd = gt ? bd[t - 1] : d;
        int   ni = gt ? bi[t - 1] : id;
        bool upd = bd[t] > d;
        bd[t] = upd ? nd : bd[t];
        bi[t] = upd ? ni : bi[t];
    }
    if (bd[0] > d) { bd[0] = d; bi[0] = id; }
}

// ======= launch 4: warp-specialized producer/consumer KNN ===================
__device__ __forceinline__ void stage_b(uint32_t sbase, int ring, int cbase, int segend, int ptid) {
    // 2 limbs x 64 rows x 8 chunks = 1024 x 16B; 256 producer threads -> 4 each
    #pragma unroll
    for (int j = 0; j < 4; j++) {
        int id = ptid + j * 256;
        int limb = id >> 9;
        int rem = id & 511;
        int row = rem >> 3, ch = rem & 7;
        int c = cbase + row;
        const __half* srcb = limb ? g_l16 : g_h16;
        uint32_t dst = sbase + SM_B + ring * (2 * B_TILE) + limb * B_TILE + row * ROWB + ch * 16;
        cp_async16(dst, srcb + (size_t)c * 64 + ch * 8, c < segend);
    }
    CP_COMMIT();
}

__global__ void __launch_bounds__(512, 1) knn_tc_kernel() {
    extern __shared__ char smem[];
    uint32_t sbase = smem_u32(smem);
    int tid = threadIdx.x, warp = tid >> 5, lane = tid & 31;
    int qblk = blockIdx.x >> 2, seg = blockIdx.x & 3;
    int qbase = qblk * QTILE;
    int segbeg = seg * SEGSZ, segend = segbeg + SEGSZ;

    float* Sp  = reinterpret_cast<float*>(smem + SM_S);    // 2 x [128][66]
    float* sqc = reinterpret_cast<float*>(smem + SM_SQ);   // [2][64]

    // ---- stage A tile (2 limbs) by all 512 threads ----
    #pragma unroll
    for (int j = 0; j < 4; j++) {
        int id = tid + j * 512;                 // 2048 chunks
        int limb = id >> 10;
        int rem = id & 1023;
        int row = rem >> 3, ch = rem & 7;
        int q = qbase + row;
        uint4 v = make_uint4(0u, 0u, 0u, 0u);
        if (q < Nn) {
            const __half* src = limb ? g_l16 : g_h16;
            v = *reinterpret_cast<const uint4*>(src + (size_t)q * 64 + ch * 8);
        }
        *reinterpret_cast<uint4*>(smem + SM_A + limb * A_TILE + row * ROWB + ch * 16) = v;
    }
    __syncthreads();

    if (warp < 8) {
        // =================== PRODUCER (warps 0-7) ===========================
        int ptid = tid;                          // 0..255
        uint32_t arow = sbase + SM_A + (warp * 16 + (lane & 15)) * ROWB + (lane >> 4) * 16;
        uint32_t brow = (lane & 15) * ROWB + (lane >> 4) * 16;
        int r0 = warp * 16 + (lane >> 2), r1 = r0 + 8;
        int cquad = 2 * (lane & 3);

        stage_b(sbase, 0, segbeg, segend, ptid);     // B[0] group

        for (int t = 0; t < NTILES; t++) {
            int sb = t & 1;
            if (t >= 2) NBAR_SYNC(3 + sb, 512);      // consumers freed S[sb]
            if (t + 1 < NTILES) {
                stage_b(sbase, (t + 1) % 3, segbeg + (t + 1) * CTILE, segend, ptid);
                CP_WAIT1();                          // B[t] complete
            } else {
                CP_WAIT0();
            }
            NBAR_SYNC(5, 256);                       // B[t] visible to all producers

            float acc[8][4];
            #pragma unroll
            for (int nt = 0; nt < 8; nt++)
                #pragma unroll
                for (int r = 0; r < 4; r++) acc[nt][r] = 0.0f;

            uint32_t bbuf = sbase + SM_B + (t % 3) * (2 * B_TILE);
            #pragma unroll
            for (int k = 0; k < 4; k++) {
                uint32_t ah[4], al[4];
                ldsm_x4(ah, arow + k * 32);
                ldsm_x4(al, arow + A_TILE + k * 32);
                #pragma unroll
                for (int p = 0; p < 4; p++) {
                    uint32_t baddr = bbuf + p * 16 * ROWB + brow + k * 32;
                    uint32_t bf[4];
                    ldsm_x4(bf, baddr);
                    mma_f16(acc[2 * p],     ah, bf[0], bf[2]);
                    mma_f16(acc[2 * p + 1], ah, bf[1], bf[3]);
                    mma_f16(acc[2 * p],     al, bf[0], bf[2]);
                    mma_f16(acc[2 * p + 1], al, bf[1], bf[3]);
                    ldsm_x4(bf, baddr + B_TILE);
                    mma_f16(acc[2 * p],     ah, bf[0], bf[2]);
                    mma_f16(acc[2 * p + 1], ah, bf[1], bf[3]);
                }
            }

            float* sp = Sp + sb * (128 * 66);
            #pragma unroll
            for (int nt = 0; nt < 8; nt++) {
                *reinterpret_cast<float2*>(&sp[r0 * 66 + nt * 8 + cquad]) = make_float2(acc[nt][0], acc[nt][1]);
                *reinterpret_cast<float2*>(&sp[r1 * 66 + nt * 8 + cquad]) = make_float2(acc[nt][2], acc[nt][3]);
            }
            NBAR_ARRIVE(1 + sb, 512);                // S[sb] full
        }
    } else {
        // =================== CONSUMER (warps 8-15) ==========================
        int ctid = tid - 256;                    // 0..255
        int srow = ctid >> 1, half = ctid & 1;
        int q = qbase + srow;
        float myq = (q < Nn) ? g_sq[q] : 0.0f;

        float bd[16]; int bi[16];
        #pragma unroll
        for (int t = 0; t < 16; t++) { bd[t] = INFF; bi[t] = -1; }

        // stage sqc[0]: 16 threads x 16B (pred: whole 4-float chunk valid)
        if (ctid < 16) {
            int c = segbeg + ctid * 4;
            cp_async16(sbase + SM_SQ + ctid * 16, g_sq + c, c + 3 < segend);
        }
        CP_COMMIT();

        for (int t = 0; t < NTILES; t++) {
            int sb = t & 1;
            NBAR_SYNC(1 + sb, 512);              // S[sb] full; all consumers past scan t-1
            if (t + 1 < NTILES) {
                if (ctid < 16) {
                    int c = segbeg + (t + 1) * CTILE + ctid * 4;
                    cp_async16(sbase + SM_SQ + ((t + 1) & 1) * 256 + ctid * 16, g_sq + c, c + 3 < segend);
                }
                CP_COMMIT();
                CP_WAIT1();                      // sqc[t] complete
            } else {
                CP_COMMIT();
                CP_WAIT0();
            }
            NBAR_SYNC(6, 256);                   // sqc[t] visible to all consumers

            int cnt = segend - (segbeg + t * CTILE);
            if (cnt > CTILE) cnt = CTILE;
            int cb = segbeg + t * CTILE + half * 32;
            const float* sp  = Sp + sb * (128 * 66) + srow * 66 + half * 32;
            const float* sqh = sqc + sb * 64 + half * 32;

            if (cnt == CTILE) {
                #pragma unroll 4
                for (int j = 0; j < 32; j += 2) {
                    float2 s2 = *reinterpret_cast<const float2*>(&sp[j]);
                    float d0 = fmaf(s2.x, -2.0f, myq + sqh[j]);
                    float d1 = fmaf(s2.y, -2.0f, myq + sqh[j + 1]);
                    if (d0 < bd[15]) topk_insert(bd, bi, d0, cb + j);
                    if (d1 < bd[15]) topk_insert(bd, bi, d1, cb + j + 1);
                }
            } else {
                int jmax = cnt - half * 32;
                if (jmax > 32) jmax = 32;
                for (int j = 0; j < jmax; j++) {
                    float d0 = fmaf(sp[j], -2.0f, myq + sqh[j]);
                    if (d0 < bd[15]) topk_insert(bd, bi, d0, cb + j);
                }
            }
            NBAR_ARRIVE(3 + sb, 512);            // S[sb] free
        }

        if (q < Nn) {
            int obase = ((q * SEGS + seg) * 2 + half) * Kk;
            #pragma unroll
            for (int t = 0; t < 16; t++) { g_cd[obase + t] = bd[t]; g_ci[obase + t] = bi[t]; }
        }
    }
}

// ======= launch 5: merge 8 lists per query ==================================
__global__ void knn_merge_kernel() {
    int q = blockIdx.x * blockDim.x + threadIdx.x;
    if (q >= Nn) return;
    float bd[16]; int bi[16];
    #pragma unroll
    for (int t = 0; t < 16; t++) { bd[t] = INFF; bi[t] = -1; }
    int base = q * NLISTS * Kk;
    for (int s = 0; s < NLISTS; s++) {
        #pragma unroll
        for (int t = 0; t < 16; t++) {
            float d = g_cd[base + s * Kk + t];
            if (d < bd[15]) topk_insert(bd, bi, d, g_ci[base + s * Kk + t]);
        }
    }
    #pragma unroll
    for (int t = 0; t < 16; t++) g_nbr[q * Kk + t] = bi[t];
}

// ======= launch 6: pair MLP (layer-1 collapsed) + max over K ================
__global__ void pair_kernel(const float* __restrict__ W2b, const float* __restrict__ b2b) {
    __shared__ float sW2b[64 * 64];
    __shared__ float sb2b[64];
    __shared__ float hbuf[8][16][64];
    int tid = threadIdx.x;
    for (int i = tid; i < 64 * 64; i += 256) sW2b[i] = W2b[i];
    if (tid < 64) sb2b[tid] = b2b[tid];
    __syncthreads();

    int warp = tid >> 5, lane = tid & 31;
    int n = blockIdx.x * 8 + warp;
    int j0 = lane, j1 = lane + 32;

    float ci0 = g_c[n * 64 + j0], ci1 = g_c[n * 64 + j1];
    float di0 = g_d[n * 64 + j0], di1 = g_d[n * 64 + j1];
    #pragma unroll
    for (int k = 0; k < 16; k++) {
        int nb = g_nbr[n * 16 + k];
        hbuf[warp][k][j0] = fmaxf(ci0 + g_d[nb * 64 + j0] - di0, 0.0f);
        hbuf[warp][k][j1] = fmaxf(ci1 + g_d[nb * 64 + j1] - di1, 0.0f);
    }
    __syncwarp();

    float a0[16], a1[16];
    #pragma unroll
    for (int k = 0; k < 16; k++) { a0[k] = 0.0f; a1[k] = 0.0f; }
    #pragma unroll 4
    for (int t = 0; t < 64; t++) {
        float w0 = sW2b[t * 64 + j0], w1 = sW2b[t * 64 + j1];
        #pragma unroll
        for (int k = 0; k < 16; k++) {
            float v = hbuf[warp][k][t];
            a0[k] += v * w0;
            a1[k] += v * w1;
        }
    }
    float b0 = sb2b[j0], b1 = sb2b[j1];
    float mx0 = 0.0f, mx1 = 0.0f;
    #pragma unroll
    for (int k = 0; k < 16; k++) {
        mx0 = fmaxf(mx0, a0[k] + b0);
        mx1 = fmaxf(mx1, a1[k] + b1);
    }
    g_x2[n * 64 + j0] = mx0;
    g_x2[n * 64 + j1] = mx1;
}

// ======= launch 7: tail (composed M_r) ======================================
__global__ void tail_kernel(const float* __restrict__ Wr2, const float* __restrict__ br2,
                            float* __restrict__ out) {
    __shared__ float sM[64 * 64];
    __shared__ float sbb[64];
    __shared__ float sWr2[192];
    __shared__ float sbuf[8][64];
    int tid = threadIdx.x, warp = tid >> 5, lane = tid & 31;
    int r = blockIdx.x / 2500;
    for (int i = tid; i < 4096; i += 256) sM[i] = g_M[r * 4096 + i];
    if (tid < 64) sbb[tid] = g_bb[r * 64 + tid];
    if (tid < 192) sWr2[tid] = Wr2[tid];
    __syncthreads();

    int l = blockIdx.x * 8 + warp;
    int i = l - r * Nn;
    int j0 = lane, j1 = lane + 32;
    float xa = g_x2[i * 64 + j0];
    float xb = g_x2[i * 64 + j1];

    float h0 = sbb[j0], h1 = sbb[j1];
    #pragma unroll 8
    for (int t = 0; t < 32; t++) {
        float xv = __shfl_sync(0xFFFFFFFFu, xa, t);
        h0 += xv * sM[t * 64 + j0];
        h1 += xv * sM[t * 64 + j1];
    }
    #pragma unroll 8
    for (int t = 0; t < 32; t++) {
        float xv = __shfl_sync(0xFFFFFFFFu, xb, t);
        h0 += xv * sM[(32 + t) * 64 + j0];
        h1 += xv * sM[(32 + t) * 64 + j1];
    }
    h0 = fmaxf(h0, 0.0f);
    h1 = fmaxf(h1, 0.0f);
    sbuf[warp][j0] = h0;
    sbuf[warp][j1] = h1;
    __syncwarp();

    if (lane < 3) {
        float o = br2[lane];
        #pragma unroll 16
        for (int k = 0; k < 64; k++) o += sbuf[warp][k] * sWr2[k * 3 + lane];
        out[l * 3 + lane] = o;
    }
}

// ---------------- launch ----------------------------------------------------
extern "C" void kernel_launch(void* const* d_in, const int* in_sizes, int n_in,
                              void* d_out, int out_size) {
    const float* dep  = (const float*)d_in[0];
    const float* W1a  = (const float*)d_in[1];
    const float* b1a  = (const float*)d_in[2];
    const float* W1b  = (const float*)d_in[3];
    const float* b1b  = (const float*)d_in[4];
    const float* W2a  = (const float*)d_in[5];
    const float* b2a  = (const float*)d_in[6];
    const float* W2b  = (const float*)d_in[7];
    const float* b2b  = (const float*)d_in[8];
    const float* We   = (const float*)d_in[9];
    const float* be   = (const float*)d_in[10];
    const float* Wp   = (const float*)d_in[11];
    const float* bp   = (const float*)d_in[12];
    const float* Wr1  = (const float*)d_in[13];
    const float* br1  = (const float*)d_in[14];
    const float* Wr2  = (const float*)d_in[15];
    const float* br2  = (const float*)d_in[16];
    const int*   eidx = (const int*)d_in[17];
    float* out = (float*)d_out;
    (void)in_sizes; (void)n_in; (void)out_size;

    cudaFuncSetAttribute(knn_tc_kernel, cudaFuncAttributeMaxDynamicSharedMemorySize, SM_TOT);

    pre_kernel<<<7504, 256>>>(dep, W1a, b1a, We, be, Wp, bp, Wr1, br1);
    edge_kernel<<<Ee / 64, 256>>>(eidx, W1b, b1b);
    sqcvt_kernel<<<Nn / 8, 256>>>(W2a, b2a);
    knn_tc_kernel<<<NQBLK * SEGS, 512, SM_TOT>>>();
    knn_merge_kernel<<<(Nn + 255) / 256, 256>>>();
    pair_kernel<<<Nn / 8, 256>>>(W2b, b2b);
    tail_kernel<<<NOUT / 8, 256>>>(Wr2, br2, out);
}

// round 16
// speedup vs baseline: 2.2180x; 2.2180x over previous
#include <cuda_runtime.h>
#include <cuda_fp16.h>
#include <cstdint>

#define Nn   20000
#define Ee   320000
#define Kk   16
#define FEATD 64
#define SEGS 4
#define SEGSZ (Nn / SEGS)        // 5000
#define NLISTS (SEGS * 2)        // 8 per query (2 half-lists per segment)
#define NOUT 80000
#define QTILE 128
#define CTILE 64
#define NQBLK ((Nn + QTILE - 1) / QTILE)       // 157
#define NTILES ((SEGSZ + CTILE - 1) / CTILE)   // 79
#define INFF __int_as_float(0x7F800000)

// ---------------- scratch (device globals; no allocations allowed) ----------
__device__ float g_x1[Nn * FEATD];
__device__ float g_sq[Nn];
__device__ int   g_nbr[Nn * Kk];
__device__ float g_x2[Nn * FEATD];
__device__ float g_cd[Nn * NLISTS * Kk];
__device__ int   g_ci[Nn * NLISTS * Kk];
__device__ int   g_thri[Nn];           // shared per-query threshold (float as int, >=0)
__device__ __half g_h16[Nn * FEATD];   // fp16 hi limb
__device__ __half g_l16[Nn * FEATD];   // fp16 lo limb
__device__ float g_u[Nn * FEATD];
__device__ float g_v[Nn * FEATD];
__device__ float g_c[Nn * FEATD];
__device__ float g_d[Nn * FEATD];
__device__ float g_M[4 * 64 * 64];
__device__ float g_bb[4 * 64];

// ======================= PTX helpers (baseline, sm_80+) =====================
__device__ __forceinline__ uint32_t smem_u32(const void* p) {
    uint32_t a;
    asm("{ .reg .u64 t; cvta.to.shared.u64 t, %1; cvt.u32.u64 %0, t; }" : "=r"(a) : "l"(p));
    return a;
}
__device__ __forceinline__ void ldsm_x4(uint32_t (&r)[4], uint32_t addr) {
    asm volatile("ldmatrix.sync.aligned.m8n8.x4.shared.b16 {%0,%1,%2,%3}, [%4];"
                 : "=r"(r[0]), "=r"(r[1]), "=r"(r[2]), "=r"(r[3]) : "r"(addr));
}
__device__ __forceinline__ void mma_f16(float (&c)[4], const uint32_t (&a)[4], const uint32_t b0, const uint32_t b1) {
    asm volatile("mma.sync.aligned.m16n8k16.row.col.f32.f16.f16.f32 "
                 "{%0,%1,%2,%3}, {%4,%5,%6,%7}, {%8,%9}, {%0,%1,%2,%3};"
                 : "+f"(c[0]), "+f"(c[1]), "+f"(c[2]), "+f"(c[3])
                 : "r"(a[0]), "r"(a[1]), "r"(a[2]), "r"(a[3]), "r"(b0), "r"(b1));
}
__device__ __forceinline__ void cp_async16(uint32_t dst, const void* src, bool pred) {
    asm volatile("{\n .reg .pred p;\n setp.ne.u32 p, %0, 0;\n"
                 " @p cp.async.ca.shared.global [%1], [%2], 16;\n}"
                 :: "r"((uint32_t)pred), "r"(dst), "l"(src));
}
#define CP_COMMIT() asm volatile("cp.async.commit_group;" ::: "memory")
#define CP_WAIT0()  asm volatile("cp.async.wait_group 0;" ::: "memory")

// ======================= smem layout for knn (bytes) ========================
#define ROWB 144                      // 64 fp16 + 8 pad (conflict-free ldmatrix)
#define A_TILE (128 * ROWB)           // 18432
#define B_TILE (64 * ROWB)            // 9216
#define SM_A   0                      // 2 limbs: +limb*A_TILE
#define SM_B   (2 * A_TILE)           // 36864 ; + buf*2*B_TILE + limb*B_TILE
#define SM_S   (SM_B + 2 * 2 * B_TILE)    // 73728 ; S[128][65] fp32 (survivors)
#define SM_SQ  (SM_S + 128 * 65 * 4)      // 107008 ; sqc[2][64]
#define SM_MYQ (SM_SQ + 512)              // 107520 ; myq[128]
#define SM_TH0 (SM_MYQ + 512)             // 108032 ; thresh half0 [128]
#define SM_TH1 (SM_TH0 + 512)             // 108544 ; thresh half1 [128]
#define SM_MSK (SM_TH1 + 512)             // 109056 ; mask[128][2] u32
#define SM_STH (SM_MSK + 1024)            // 110080 ; shared-global thr cache [128]
#define SM_TOT (SM_STH + 512)             // 110592 -> 2 CTAs/SM

// ======= launch 1: zero x1 + u/v precompute + tail-M precompute =============
__global__ void pre_kernel(const float* __restrict__ dep,
                           const float* __restrict__ W1a, const float* __restrict__ b1a,
                           const float* __restrict__ We,  const float* __restrict__ be,
                           const float* __restrict__ Wp,  const float* __restrict__ bp,
                           const float* __restrict__ Wr1, const float* __restrict__ br1) {
    int b = blockIdx.x, tid = threadIdx.x;
    if (b < 5000) {
        g_x1[b * 256 + tid] = 0.0f;
        return;
    }
    if (b < 7500) {
        int warp = tid >> 5, lane = tid & 31;
        int n = (b - 5000) * 8 + warp;
        float x0 = dep[3 * n], x1v = dep[3 * n + 1], x2v = dep[3 * n + 2];
        int j0 = lane, j1 = lane + 32;
        float u0 = b1a[j0] + x0 * W1a[j0] + x1v * W1a[64 + j0] + x2v * W1a[128 + j0];
        float u1 = b1a[j1] + x0 * W1a[j1] + x1v * W1a[64 + j1] + x2v * W1a[128 + j1];
        float v0 = x0 * W1a[192 + j0] + x1v * W1a[256 + j0] + x2v * W1a[320 + j0];
        float v1 = x0 * W1a[192 + j1] + x1v * W1a[256 + j1] + x2v * W1a[320 + j1];
        g_u[n * 64 + j0] = u0; g_u[n * 64 + j1] = u1;
        g_v[n * 64 + j0] = v0; g_v[n * 64 + j1] = v1;
        return;
    }
    {
        int r = b - 7500;
        __shared__ float sA[4096], sB[4096], sT[4096], sTb[64];
        for (int i = tid; i < 4096; i += 256) {
            int k = i >> 6, a = i & 63;
            sA[i] = We[k * 256 + r * 64 + a];
        }
        for (int i = tid; i < 4096; i += 256) sB[i] = Wp[i];
        __syncthreads();
        for (int i = tid; i < 4096; i += 256) {
            int k = i >> 6, bb = i & 63;
            float s = 0.0f;
            #pragma unroll 16
            for (int a = 0; a < 64; a++) s += sA[k * 64 + a] * sB[a * 64 + bb];
            sT[i] = s;
        }
        if (tid < 64) {
            float s = bp[tid];
            #pragma unroll 16
            for (int a = 0; a < 64; a++) s += be[r * 64 + a] * sB[a * 64 + tid];
            sTb[tid] = s;
        }
        __syncthreads();
        for (int i = tid; i < 4096; i += 256) sB[i] = Wr1[i];
        __syncthreads();
        for (int i = tid; i < 4096; i += 256) {
            int k = i >> 6, c = i & 63;
            float s = 0.0f;
            #pragma unroll 16
            for (int bb = 0; bb < 64; bb++) s += sT[k * 64 + bb] * sB[bb * 64 + c];
            g_M[r * 4096 + i] = s;
        }
        if (tid < 64) {
            float s = br1[tid];
            #pragma unroll 16
            for (int bb = 0; bb < 64; bb++) s += sTb[bb] * sB[bb * 64 + tid];
            g_bb[r * 64 + tid] = s;
        }
    }
}

// ======= launch 2: edge MLP (layer-1 collapsed) + segment max ===============
__global__ void edge_kernel(const int* __restrict__ eidx,
                            const float* __restrict__ W1b, const float* __restrict__ b1b) {
    __shared__ float sW1b[64 * 64];
    __shared__ float sb1b[64];
    __shared__ float hbuf[8][8][66];
    int tid = threadIdx.x;
    for (int i = tid; i < 64 * 64; i += 256) sW1b[i] = W1b[i];
    if (tid < 64) sb1b[tid] = b1b[tid];
    __syncthreads();

    int warp = tid >> 5, lane = tid & 31;
    int j0 = lane, j1 = lane + 32;
    int ebase = blockIdx.x * 64 + warp * 8;
    int* x1i = reinterpret_cast<int*>(g_x1);

    int ds[8];
    #pragma unroll
    for (int e = 0; e < 8; e++) {
        int s = eidx[ebase + e], d = eidx[Ee + ebase + e];
        ds[e] = d;
        float h0 = fmaxf(g_u[d * 64 + j0] + g_v[s * 64 + j0] - g_v[d * 64 + j0], 0.0f);
        float h1 = fmaxf(g_u[d * 64 + j1] + g_v[s * 64 + j1] - g_v[d * 64 + j1], 0.0f);
        hbuf[warp][e][j0] = h0;
        hbuf[warp][e][j1] = h1;
    }
    __syncwarp();

    float a0[8], a1[8];
    #pragma unroll
    for (int e = 0; e < 8; e++) { a0[e] = sb1b[j0]; a1[e] = sb1b[j1]; }
    #pragma unroll 8
    for (int t = 0; t < 64; t++) {
        float w0 = sW1b[t * 64 + j0], w1 = sW1b[t * 64 + j1];
        #pragma unroll
        for (int e = 0; e < 8; e++) {
            float v = hbuf[warp][e][t];
            a0[e] += v * w0;
            a1[e] += v * w1;
        }
    }
    #pragma unroll
    for (int e = 0; e < 8; e++) {
        atomicMax(&x1i[ds[e] * 64 + j0], __float_as_int(fmaxf(a0[e], 0.0f)));
        atomicMax(&x1i[ds[e] * 64 + j1], __float_as_int(fmaxf(a1[e], 0.0f)));
    }
}

// ======= launch 3: sq + fp16 2-limb split + pair c/d + thr init =============
__global__ void sqcvt_kernel(const float* __restrict__ W2a, const float* __restrict__ b2a) {
    __shared__ float sW2a[128 * 64];
    __shared__ float sb2a[64];
    int tid = threadIdx.x;
    for (int i = tid; i < 128 * 64; i += 256) sW2a[i] = W2a[i];
    if (tid < 64) sb2a[tid] = b2a[tid];
    __syncthreads();

    int warp = tid >> 5, lane = tid & 31;
    int n = blockIdx.x * 8 + warp;
    int j0 = lane, j1 = lane + 32;
    float a = g_x1[n * 64 + j0];
    float b = g_x1[n * 64 + j1];

    float s = a * a + b * b;
    #pragma unroll
    for (int o = 16; o; o >>= 1) s += __shfl_xor_sync(0xFFFFFFFFu, s, o);
    if (lane == 0) g_sq[n] = s;
    if (lane == 1) g_thri[n] = 0x7F800000;

    {
        __half h = __float2half(a);
        g_h16[n * 64 + j0] = h;
        g_l16[n * 64 + j0] = __float2half(a - __half2float(h));
        h = __float2half(b);
        g_h16[n * 64 + j1] = h;
        g_l16[n * 64 + j1] = __float2half(b - __half2float(h));
    }

    float c0 = sb2a[j0], c1 = sb2a[j1], d0 = 0.0f, d1 = 0.0f;
    #pragma unroll 8
    for (int t = 0; t < 32; t++) {
        float xv = __shfl_sync(0xFFFFFFFFu, a, t);
        c0 += xv * sW2a[t * 64 + j0];
        c1 += xv * sW2a[t * 64 + j1];
        d0 += xv * sW2a[(64 + t) * 64 + j0];
        d1 += xv * sW2a[(64 + t) * 64 + j1];
    }
    #pragma unroll 8
    for (int t = 0; t < 32; t++) {
        float xv = __shfl_sync(0xFFFFFFFFu, b, t);
        c0 += xv * sW2a[(32 + t) * 64 + j0];
        c1 += xv * sW2a[(32 + t) * 64 + j1];
        d0 += xv * sW2a[(96 + t) * 64 + j0];
        d1 += xv * sW2a[(96 + t) * 64 + j1];
    }
    g_c[n * 64 + j0] = c0; g_c[n * 64 + j1] = c1;
    g_d[n * 64 + j0] = d0; g_d[n * 64 + j1] = d1;
}

// fully-predicated register top-16 insertion
__device__ __forceinline__ void topk_insert(float (&bd)[16], int (&bi)[16], float d, int id) {
    #pragma unroll
    for (int t = 15; t > 0; t--) {
        bool gt  = bd[t - 1] > d;
        float nd = gt ? bd[t - 1] : d;
        int   ni = gt ? bi[t - 1] : id;
        bool upd = bd[t] > d;
        bd[t] = upd ? nd : bd[t];
        bi[t] = upd ? ni : bi[t];
    }
    if (bd[0] > d) { bd[0] = d; bi[0] = id; }
}

// ======= launch 4: fp16 2-limb KNN, warp-local scan, 1 barrier/tile =========
__device__ __forceinline__ void knn_prefetch(uint32_t sbase, int buf,
                                             int cbase, int segend, int tid) {
    #pragma unroll
    for (int j = 0; j < 4; j++) {
        int id = tid + j * 256;
        int limb = id >> 9;
        int rem = id & 511;
        int row = rem >> 3, ch = rem & 7;
        int c = cbase + row;
        const __half* srcb = limb ? g_l16 : g_h16;
        uint32_t dst = sbase + SM_B + buf * (2 * B_TILE) + limb * B_TILE + row * ROWB + ch * 16;
        cp_async16(dst, srcb + (size_t)c * 64 + ch * 8, c < segend);
    }
    CP_COMMIT();
}

__global__ void __launch_bounds__(256, 2) knn_tc_kernel() {
    extern __shared__ char smem[];
    uint32_t sbase = smem_u32(smem);
    int tid = threadIdx.x, warp = tid >> 5, lane = tid & 31;
    int qblk = blockIdx.x >> 2, seg = blockIdx.x & 3;
    int qbase = qblk * QTILE;
    int segbeg = seg * SEGSZ, segend = segbeg + SEGSZ;

    float*    Sp    = reinterpret_cast<float*>(smem + SM_S);
    float*    sqc   = reinterpret_cast<float*>(smem + SM_SQ);
    float*    myqs  = reinterpret_cast<float*>(smem + SM_MYQ);
    float*    th0s  = reinterpret_cast<float*>(smem + SM_TH0);
    float*    th1s  = reinterpret_cast<float*>(smem + SM_TH1);
    uint32_t* maskb = reinterpret_cast<uint32_t*>(smem + SM_MSK);
    float*    sthr  = reinterpret_cast<float*>(smem + SM_STH);

    // ---- stage A tile (2 limbs), zero-padded ----
    #pragma unroll
    for (int j = 0; j < 8; j++) {
        int id = tid + j * 256;
        int limb = id >> 10;
        int rem = id & 1023;
        int row = rem >> 3, ch = rem & 7;
        int q = qbase + row;
        uint4 v = make_uint4(0u, 0u, 0u, 0u);
        if (q < Nn) {
            const __half* src = limb ? g_l16 : g_h16;
            v = *reinterpret_cast<const uint4*>(src + (size_t)q * 64 + ch * 8);
        }
        *reinterpret_cast<uint4*>(smem + SM_A + limb * A_TILE + row * ROWB + ch * 16) = v;
    }
    knn_prefetch(sbase, 0, segbeg, segend, tid);
    if (tid < 64) {
        int c = segbeg + tid;
        sqc[tid] = (c < segend) ? g_sq[c] : INFF;
    }
    if (tid < 128) {
        int q = qbase + tid;
        myqs[tid] = (q < Nn) ? g_sq[q] : 0.0f;
        th0s[tid] = INFF;
        th1s[tid] = INFF;
        sthr[tid] = INFF;
        maskb[2 * tid] = 0u;
        maskb[2 * tid + 1] = 0u;
    }
    CP_WAIT0();
    __syncthreads();

    // per-thread state
    float bd[16]; int bi[16];
    #pragma unroll
    for (int t = 0; t < 16; t++) { bd[t] = INFF; bi[t] = -1; }

    // eval ownership (MMA fragment rows)
    int r0 = warp * 16 + (lane >> 2), r1 = r0 + 8;
    int cquad = 2 * (lane & 3);
    float mq0 = myqs[r0], mq1 = myqs[r1];
    uint32_t arow = sbase + SM_A + (warp * 16 + (lane & 15)) * ROWB + (lane >> 4) * 16;
    // scan ownership (warp-local): lane<16 -> word0, lane>=16 -> word1
    int srow = warp * 16 + (lane & 15);
    int sword = lane >> 4;
    float* thMine = sword ? th1s : th0s;

    for (int t = 0; t < NTILES; t++) {
        int buf = t & 1;

        // ---- MMA: k-major, 3-pass fp16 2-limb (hh + lh + hl) ----
        float acc[8][4];
        #pragma unroll
        for (int nt = 0; nt < 8; nt++)
            #pragma unroll
            for (int r = 0; r < 4; r++) acc[nt][r] = 0.0f;

        uint32_t brow = (lane & 15) * ROWB + (lane >> 4) * 16;
        uint32_t bbuf = sbase + SM_B + buf * (2 * B_TILE);
        #pragma unroll
        for (int k = 0; k < 4; k++) {
            uint32_t ah[4], al[4];
            ldsm_x4(ah, arow + k * 32);
            ldsm_x4(al, arow + A_TILE + k * 32);
            #pragma unroll
            for (int p = 0; p < 4; p++) {
                uint32_t baddr = bbuf + p * 16 * ROWB + brow + k * 32;
                uint32_t bf[4];
                ldsm_x4(bf, baddr);
                mma_f16(acc[2 * p],     ah, bf[0], bf[2]);
                mma_f16(acc[2 * p + 1], ah, bf[1], bf[3]);
                mma_f16(acc[2 * p],     al, bf[0], bf[2]);
                mma_f16(acc[2 * p + 1], al, bf[1], bf[3]);
                ldsm_x4(bf, baddr + B_TILE);
                mma_f16(acc[2 * p],     ah, bf[0], bf[2]);
                mma_f16(acc[2 * p + 1], ah, bf[1], bf[3]);
            }
        }

        // ---- prefetch next B/sqc + refresh shared threshold (overlaps eval/scan)
        if (t + 1 < NTILES) {
            knn_prefetch(sbase, (t + 1) & 1, segbeg + (t + 1) * CTILE, segend, tid);
            if (tid < 64) {
                int c = segbeg + (t + 1) * CTILE + tid;
                sqc[((t + 1) & 1) * 64 + tid] = (c < segend) ? g_sq[c] : INFF;
            }
        }
        if (tid < 128) {
            int q = qbase + tid;
            if (q < Nn) sthr[tid] = __int_as_float(__ldcg(&g_thri[q]));
        }

        // ---- in-fragment eval + threshold filter ----
        {
            float tha = fminf(fminf(th0s[r0], th1s[r0]), sthr[r0]);
            float thb = fminf(fminf(th0s[r1], th1s[r1]), sthr[r1]);
            #pragma unroll
            for (int nt = 0; nt < 8; nt++) {
                float2 sqp = *reinterpret_cast<const float2*>(&sqc[buf * 64 + nt * 8 + cquad]);
                float d00 = fmaf(acc[nt][0], -2.0f, mq0 + sqp.x);
                float d01 = fmaf(acc[nt][1], -2.0f, mq0 + sqp.y);
                float d10 = fmaf(acc[nt][2], -2.0f, mq1 + sqp.x);
                float d11 = fmaf(acc[nt][3], -2.0f, mq1 + sqp.y);
                int c0 = nt * 8 + cquad;
                int word = nt >> 2;
                uint32_t b0 = 1u << (c0 & 31);
                if (d00 < tha) { Sp[r0 * 65 + c0]     = d00; atomicOr(&maskb[r0 * 2 + word], b0); }
                if (d01 < tha) { Sp[r0 * 65 + c0 + 1] = d01; atomicOr(&maskb[r0 * 2 + word], b0 << 1); }
                if (d10 < thb) { Sp[r1 * 65 + c0]     = d10; atomicOr(&maskb[r1 * 2 + word], b0); }
                if (d11 < thb) { Sp[r1 * 65 + c0 + 1] = d11; atomicOr(&maskb[r1 * 2 + word], b0 << 1); }
            }
        }
        __syncwarp();

        // ---- warp-local sparse scan: lane owns (srow, sword) ----
        {
            uint32_t m = maskb[2 * srow + sword];
            if (m) {
                maskb[2 * srow + sword] = 0u;
                int cb = segbeg + t * CTILE + sword * 32;
                const float* sr = &Sp[srow * 65 + sword * 32];
                while (m) {
                    int b = __ffs(m) - 1; m &= m - 1;
                    float d2 = sr[b];
                    if (d2 < bd[15]) topk_insert(bd, bi, d2, cb + b);
                }
                thMine[srow] = bd[15];
                atomicMin(&g_thri[qbase + srow], __float_as_int(fmaxf(bd[15], 0.0f)));
            }
        }

        if (t + 1 < NTILES) CP_WAIT0();
        __syncthreads();   // single barrier per tile
    }

    if (qbase + srow < Nn) {
        int obase = (((qbase + srow) * SEGS + seg) * 2 + sword) * Kk;
        #pragma unroll
        for (int t = 0; t < 16; t++) { g_cd[obase + t] = bd[t]; g_ci[obase + t] = bi[t]; }
    }
}

// ======= launch 5: merge 8 lists per query ==================================
__global__ void knn_merge_kernel() {
    int q = blockIdx.x * blockDim.x + threadIdx.x;
    if (q >= Nn) return;
    float bd[16]; int bi[16];
    #pragma unroll
    for (int t = 0; t < 16; t++) { bd[t] = INFF; bi[t] = -1; }
    int base = q * NLISTS * Kk;
    for (int s = 0; s < NLISTS; s++) {
        #pragma unroll
        for (int t = 0; t < 16; t++) {
            float d = g_cd[base + s * Kk + t];
            if (d < bd[15]) topk_insert(bd, bi, d, g_ci[base + s * Kk + t]);
        }
    }
    #pragma unroll
    for (int t = 0; t < 16; t++) g_nbr[q * Kk + t] = bi[t];
}

// ======= launch 6: pair MLP (layer-1 collapsed) + max over K ================
__global__ void pair_kernel(const float* __restrict__ W2b, const float* __restrict__ b2b) {
    __shared__ float sW2b[64 * 64];
    __shared__ float sb2b[64];
    __shared__ float hbuf[8][16][64];
    int tid = threadIdx.x;
    for (int i = tid; i < 64 * 64; i += 256) sW2b[i] = W2b[i];
    if (tid < 64) sb2b[tid] = b2b[tid];
    __syncthreads();

    int warp = tid >> 5, lane = tid & 31;
    int n = blockIdx.x * 8 + warp;
    int j0 = lane, j1 = lane + 32;

    float ci0 = g_c[n * 64 + j0], ci1 = g_c[n * 64 + j1];
    float di0 = g_d[n * 64 + j0], di1 = g_d[n * 64 + j1];
    #pragma unroll
    for (int k = 0; k < 16; k++) {
        int nb = g_nbr[n * 16 + k];
        hbuf[warp][k][j0] = fmaxf(ci0 + g_d[nb * 64 + j0] - di0, 0.0f);
        hbuf[warp][k][j1] = fmaxf(ci1 + g_d[nb * 64 + j1] - di1, 0.0f);
    }
    __syncwarp();

    float a0[16], a1[16];
    #pragma unroll
    for (int k = 0; k < 16; k++) { a0[k] = 0.0f; a1[k] = 0.0f; }
    #pragma unroll 4
    for (int t = 0; t < 64; t++) {
        float w0 = sW2b[t * 64 + j0], w1 = sW2b[t * 64 + j1];
        #pragma unroll
        for (int k = 0; k < 16; k++) {
            float v = hbuf[warp][k][t];
            a0[k] += v * w0;
            a1[k] += v * w1;
        }
    }
    float b0 = sb2b[j0], b1 = sb2b[j1];
    float mx0 = 0.0f, mx1 = 0.0f;
    #pragma unroll
    for (int k = 0; k < 16; k++) {
        mx0 = fmaxf(mx0, a0[k] + b0);
        mx1 = fmaxf(mx1, a1[k] + b1);
    }
    g_x2[n * 64 + j0] = mx0;
    g_x2[n * 64 + j1] = mx1;
}

// ======= launch 7: tail (composed M_r) ======================================
__global__ void tail_kernel(const float* __restrict__ Wr2, const float* __restrict__ br2,
                            float* __restrict__ out) {
    __shared__ float sM[64 * 64];
    __shared__ float sbb[64];
    __shared__ float sWr2[192];
    __shared__ float sbuf[8][64];
    int tid = threadIdx.x, warp = tid >> 5, lane = tid & 31;
    int r = blockIdx.x / 2500;
    for (int i = tid; i < 4096; i += 256) sM[i] = g_M[r * 4096 + i];
    if (tid < 64) sbb[tid] = g_bb[r * 64 + tid];
    if (tid < 192) sWr2[tid] = Wr2[tid];
    __syncthreads();

    int l = blockIdx.x * 8 + warp;
    int i = l - r * Nn;
    int j0 = lane, j1 = lane + 32;
    float xa = g_x2[i * 64 + j0];
    float xb = g_x2[i * 64 + j1];

    float h0 = sbb[j0], h1 = sbb[j1];
    #pragma unroll 8
    for (int t = 0; t < 32; t++) {
        float xv = __shfl_sync(0xFFFFFFFFu, xa, t);
        h0 += xv * sM[t * 64 + j0];
        h1 += xv * sM[t * 64 + j1];
    }
    #pragma unroll 8
    for (int t = 0; t < 32; t++) {
        float xv = __shfl_sync(0xFFFFFFFFu, xb, t);
        h0 += xv * sM[(32 + t) * 64 + j0];
        h1 += xv * sM[(32 + t) * 64 + j1];
    }
    h0 = fmaxf(h0, 0.0f);
    h1 = fmaxf(h1, 0.0f);
    sbuf[warp][j0] = h0;
    sbuf[warp][j1] = h1;
    __syncwarp();

    if (lane < 3) {
        float o = br2[lane];
        #pragma unroll 16
        for (int k = 0; k < 64; k++) o += sbuf[warp][k] * sWr2[k * 3 + lane];
        out[l * 3 + lane] = o;
    }
}

// ---------------- launch ----------------------------------------------------
extern "C" void kernel_launch(void* const* d_in, const int* in_sizes, int n_in,
                              void* d_out, int out_size) {
    const float* dep  = (const float*)d_in[0];
    const float* W1a  = (const float*)d_in[1];
    const float* b1a  = (const float*)d_in[2];
    const float* W1b  = (const float*)d_in[3];
    const float* b1b  = (const float*)d_in[4];
    const float* W2a  = (const float*)d_in[5];
    const float* b2a  = (const float*)d_in[6];
    const float* W2b  = (const float*)d_in[7];
    const float* b2b  = (const float*)d_in[8];
    const float* We   = (const float*)d_in[9];
    const float* be   = (const float*)d_in[10];
    const float* Wp   = (const float*)d_in[11];
    const float* bp   = (const float*)d_in[12];
    const float* Wr1  = (const float*)d_in[13];
    const float* br1  = (const float*)d_in[14];
    const float* Wr2  = (const float*)d_in[15];
    const float* br2  = (const float*)d_in[16];
    const int*   eidx = (const int*)d_in[17];
    float* out = (float*)d_out;
    (void)in_sizes; (void)n_in; (void)out_size;

    cudaFuncSetAttribute(knn_tc_kernel, cudaFuncAttributeMaxDynamicSharedMemorySize, SM_TOT);

    pre_kernel<<<7504, 256>>>(dep, W1a, b1a, We, be, Wp, bp, Wr1, br1);
    edge_kernel<<<Ee / 64, 256>>>(eidx, W1b, b1b);
    sqcvt_kernel<<<Nn / 8, 256>>>(W2a, b2a);
    knn_tc_kernel<<<NQBLK * SEGS, 256, SM_TOT>>>();
    knn_merge_kernel<<<(Nn + 255) / 256, 256>>>();
    pair_kernel<<<Nn / 8, 256>>>(W2b, b2b);
    tail_kernel<<<NOUT / 8, 256>>>(Wr2, br2, out);
}

// round 17
// speedup vs baseline: 2.3590x; 1.0636x over previous
#include <cuda_runtime.h>
#include <cuda_fp16.h>
#include <cstdint>

#define Nn   20000
#define Ee   320000
#define Kk   16
#define FEATD 64
#define SEGS 8
#define SEGSZ (Nn / SEGS)        // 2500
#define NLISTS SEGS              // 8 per query
#define NOUT 80000
#define QTILE 128
#define CTILE 64
#define NQBLK ((Nn + QTILE - 1) / QTILE)       // 157
#define NTILES ((SEGSZ + CTILE - 1) / CTILE)   // 40
#define INFF __int_as_float(0x7F800000)

// ---------------- scratch (device globals; no allocations allowed) ----------
__device__ float g_x1[Nn * FEATD];
__device__ float g_sq[Nn];
__device__ int   g_nbr[Nn * Kk];
__device__ float g_x2[Nn * FEATD];
__device__ float g_cd[Nn * NLISTS * Kk];
__device__ int   g_ci[Nn * NLISTS * Kk];
__device__ int   g_thri[Nn];           // shared per-query threshold (float as int, >=0)
__device__ __half g_h16[Nn * FEATD];   // fp16 hi limb
__device__ __half g_l16[Nn * FEATD];   // fp16 lo limb
__device__ float g_u[Nn * FEATD];
__device__ float g_v[Nn * FEATD];
__device__ float g_c[Nn * FEATD];
__device__ float g_d[Nn * FEATD];
__device__ float g_M[4 * 64 * 64];
__device__ float g_bb[4 * 64];

// ======================= PTX helpers (baseline, sm_80+) =====================
__device__ __forceinline__ uint32_t smem_u32(const void* p) {
    uint32_t a;
    asm("{ .reg .u64 t; cvta.to.shared.u64 t, %1; cvt.u32.u64 %0, t; }" : "=r"(a) : "l"(p));
    return a;
}
__device__ __forceinline__ void ldsm_x4(uint32_t (&r)[4], uint32_t addr) {
    asm volatile("ldmatrix.sync.aligned.m8n8.x4.shared.b16 {%0,%1,%2,%3}, [%4];"
                 : "=r"(r[0]), "=r"(r[1]), "=r"(r[2]), "=r"(r[3]) : "r"(addr));
}
__device__ __forceinline__ void mma_f16(float (&c)[4], const uint32_t (&a)[4], const uint32_t b0, const uint32_t b1) {
    asm volatile("mma.sync.aligned.m16n8k16.row.col.f32.f16.f16.f32 "
                 "{%0,%1,%2,%3}, {%4,%5,%6,%7}, {%8,%9}, {%0,%1,%2,%3};"
                 : "+f"(c[0]), "+f"(c[1]), "+f"(c[2]), "+f"(c[3])
                 : "r"(a[0]), "r"(a[1]), "r"(a[2]), "r"(a[3]), "r"(b0), "r"(b1));
}
__device__ __forceinline__ void cp_async16(uint32_t dst, const void* src, bool pred) {
    asm volatile("{\n .reg .pred p;\n setp.ne.u32 p, %0, 0;\n"
                 " @p cp.async.ca.shared.global [%1], [%2], 16;\n}"
                 :: "r"((uint32_t)pred), "r"(dst), "l"(src));
}
#define CP_COMMIT() asm volatile("cp.async.commit_group;" ::: "memory")
#define CP_WAIT1()  asm volatile("cp.async.wait_group 1;" ::: "memory")
#define CP_WAIT0()  asm volatile("cp.async.wait_group 0;" ::: "memory")

// ======================= smem layout for knn (bytes) ========================
#define ROWB 144                      // 64 fp16 + 8 pad (conflict-free ldmatrix)
#define A_TILE (128 * ROWB)           // 18432
#define B_TILE (64 * ROWB)            // 9216
#define SM_A   0                      // 2 limbs: +limb*A_TILE
#define SM_B   (2 * A_TILE)           // 36864 ; + buf*2*B_TILE + limb*B_TILE
#define SM_S   (SM_B + 2 * 2 * B_TILE)    // 73728 ; S[128][65] fp32 (survivors)
#define SM_SQ  (SM_S + 128 * 65 * 4)      // 107008 ; sqc[2][64]
#define SM_MYQ (SM_SQ + 512)              // 107520 ; myq[128]
#define SM_TH  (SM_MYQ + 512)             // 108032 ; thresh[128]
#define SM_MSK (SM_TH + 512)              // 108544 ; mask[128][2] u32
#define SM_STH (SM_MSK + 1024)            // 109568 ; shared-global thr cache [128]
#define SM_TOT (SM_STH + 512)             // 110080 -> 2 CTAs/SM

// ======= launch 1: zero x1 + u/v precompute + tail-M precompute =============
__global__ void pre_kernel(const float* __restrict__ dep,
                           const float* __restrict__ W1a, const float* __restrict__ b1a,
                           const float* __restrict__ We,  const float* __restrict__ be,
                           const float* __restrict__ Wp,  const float* __restrict__ bp,
                           const float* __restrict__ Wr1, const float* __restrict__ br1) {
    int b = blockIdx.x, tid = threadIdx.x;
    if (b < 5000) {
        g_x1[b * 256 + tid] = 0.0f;
        return;
    }
    if (b < 7500) {
        int warp = tid >> 5, lane = tid & 31;
        int n = (b - 5000) * 8 + warp;
        float x0 = dep[3 * n], x1v = dep[3 * n + 1], x2v = dep[3 * n + 2];
        int j0 = lane, j1 = lane + 32;
        float u0 = b1a[j0] + x0 * W1a[j0] + x1v * W1a[64 + j0] + x2v * W1a[128 + j0];
        float u1 = b1a[j1] + x0 * W1a[j1] + x1v * W1a[64 + j1] + x2v * W1a[128 + j1];
        float v0 = x0 * W1a[192 + j0] + x1v * W1a[256 + j0] + x2v * W1a[320 + j0];
        float v1 = x0 * W1a[192 + j1] + x1v * W1a[256 + j1] + x2v * W1a[320 + j1];
        g_u[n * 64 + j0] = u0; g_u[n * 64 + j1] = u1;
        g_v[n * 64 + j0] = v0; g_v[n * 64 + j1] = v1;
        return;
    }
    {
        int r = b - 7500;
        __shared__ float sA[4096], sB[4096], sT[4096], sTb[64];
        for (int i = tid; i < 4096; i += 256) {
            int k = i >> 6, a = i & 63;
            sA[i] = We[k * 256 + r * 64 + a];
        }
        for (int i = tid; i < 4096; i += 256) sB[i] = Wp[i];
        __syncthreads();
        for (int i = tid; i < 4096; i += 256) {
            int k = i >> 6, bb = i & 63;
            float s = 0.0f;
            #pragma unroll 16
            for (int a = 0; a < 64; a++) s += sA[k * 64 + a] * sB[a * 64 + bb];
            sT[i] = s;
        }
        if (tid < 64) {
            float s = bp[tid];
            #pragma unroll 16
            for (int a = 0; a < 64; a++) s += be[r * 64 + a] * sB[a * 64 + tid];
            sTb[tid] = s;
        }
        __syncthreads();
        for (int i = tid; i < 4096; i += 256) sB[i] = Wr1[i];
        __syncthreads();
        for (int i = tid; i < 4096; i += 256) {
            int k = i >> 6, c = i & 63;
            float s = 0.0f;
            #pragma unroll 16
            for (int bb = 0; bb < 64; bb++) s += sT[k * 64 + bb] * sB[bb * 64 + c];
            g_M[r * 4096 + i] = s;
        }
        if (tid < 64) {
            float s = br1[tid];
            #pragma unroll 16
            for (int bb = 0; bb < 64; bb++) s += sTb[bb] * sB[bb * 64 + tid];
            g_bb[r * 64 + tid] = s;
        }
    }
}

// ======= launch 2: edge MLP (layer-1 collapsed) + segment max ===============
__global__ void edge_kernel(const int* __restrict__ eidx,
                            const float* __restrict__ W1b, const float* __restrict__ b1b) {
    __shared__ float sW1b[64 * 64];
    __shared__ float sb1b[64];
    __shared__ float hbuf[8][8][66];
    int tid = threadIdx.x;
    for (int i = tid; i < 64 * 64; i += 256) sW1b[i] = W1b[i];
    if (tid < 64) sb1b[tid] = b1b[tid];
    __syncthreads();

    int warp = tid >> 5, lane = tid & 31;
    int j0 = lane, j1 = lane + 32;
    int ebase = blockIdx.x * 64 + warp * 8;
    int* x1i = reinterpret_cast<int*>(g_x1);

    int ds[8];
    #pragma unroll
    for (int e = 0; e < 8; e++) {
        int s = eidx[ebase + e], d = eidx[Ee + ebase + e];
        ds[e] = d;
        float h0 = fmaxf(g_u[d * 64 + j0] + g_v[s * 64 + j0] - g_v[d * 64 + j0], 0.0f);
        float h1 = fmaxf(g_u[d * 64 + j1] + g_v[s * 64 + j1] - g_v[d * 64 + j1], 0.0f);
        hbuf[warp][e][j0] = h0;
        hbuf[warp][e][j1] = h1;
    }
    __syncwarp();

    float a0[8], a1[8];
    #pragma unroll
    for (int e = 0; e < 8; e++) { a0[e] = sb1b[j0]; a1[e] = sb1b[j1]; }
    #pragma unroll 8
    for (int t = 0; t < 64; t++) {
        float w0 = sW1b[t * 64 + j0], w1 = sW1b[t * 64 + j1];
        #pragma unroll
        for (int e = 0; e < 8; e++) {
            float v = hbuf[warp][e][t];
            a0[e] += v * w0;
            a1[e] += v * w1;
        }
    }
    #pragma unroll
    for (int e = 0; e < 8; e++) {
        atomicMax(&x1i[ds[e] * 64 + j0], __float_as_int(fmaxf(a0[e], 0.0f)));
        atomicMax(&x1i[ds[e] * 64 + j1], __float_as_int(fmaxf(a1[e], 0.0f)));
    }
}

// ======= launch 3: sq + fp16 2-limb split + pair c/d + thr init =============
__global__ void sqcvt_kernel(const float* __restrict__ W2a, const float* __restrict__ b2a) {
    __shared__ float sW2a[128 * 64];
    __shared__ float sb2a[64];
    int tid = threadIdx.x;
    for (int i = tid; i < 128 * 64; i += 256) sW2a[i] = W2a[i];
    if (tid < 64) sb2a[tid] = b2a[tid];
    __syncthreads();

    int warp = tid >> 5, lane = tid & 31;
    int n = blockIdx.x * 8 + warp;
    int j0 = lane, j1 = lane + 32;
    float a = g_x1[n * 64 + j0];
    float b = g_x1[n * 64 + j1];

    float s = a * a + b * b;
    #pragma unroll
    for (int o = 16; o; o >>= 1) s += __shfl_xor_sync(0xFFFFFFFFu, s, o);
    if (lane == 0) g_sq[n] = s;
    if (lane == 1) g_thri[n] = 0x7F800000;

    {
        __half h = __float2half(a);
        g_h16[n * 64 + j0] = h;
        g_l16[n * 64 + j0] = __float2half(a - __half2float(h));
        h = __float2half(b);
        g_h16[n * 64 + j1] = h;
        g_l16[n * 64 + j1] = __float2half(b - __half2float(h));
    }

    float c0 = sb2a[j0], c1 = sb2a[j1], d0 = 0.0f, d1 = 0.0f;
    #pragma unroll 8
    for (int t = 0; t < 32; t++) {
        float xv = __shfl_sync(0xFFFFFFFFu, a, t);
        c0 += xv * sW2a[t * 64 + j0];
        c1 += xv * sW2a[t * 64 + j1];
        d0 += xv * sW2a[(64 + t) * 64 + j0];
        d1 += xv * sW2a[(64 + t) * 64 + j1];
    }
    #pragma unroll 8
    for (int t = 0; t < 32; t++) {
        float xv = __shfl_sync(0xFFFFFFFFu, b, t);
        c0 += xv * sW2a[(32 + t) * 64 + j0];
        c1 += xv * sW2a[(32 + t) * 64 + j1];
        d0 += xv * sW2a[(96 + t) * 64 + j0];
        d1 += xv * sW2a[(96 + t) * 64 + j1];
    }
    g_c[n * 64 + j0] = c0; g_c[n * 64 + j1] = c1;
    g_d[n * 64 + j0] = d0; g_d[n * 64 + j1] = d1;
}

// fully-predicated register top-16 insertion
__device__ __forceinline__ void topk_insert(float (&bd)[16], int (&bi)[16], float d, int id) {
    #pragma unroll
    for (int t = 15; t > 0; t--) {
        bool gt  = bd[t - 1] > d;
        float nd = gt ? bd[t - 1] : d;
        int   ni = gt ? bi[t - 1] : id;
        bool upd = bd[t] > d;
        bd[t] = upd ? nd : bd[t];
        bi[t] = upd ? ni : bi[t];
    }
    if (bd[0] > d) { bd[0] = d; bi[0] = id; }
}

// ======= launch 4: mma.sync fp16 KNN with shared-threshold filter ===========
__device__ __forceinline__ void knn_prefetch(uint32_t sbase, int buf,
                                             int cbase, int segend, int tid) {
    #pragma unroll
    for (int j = 0; j < 4; j++) {
        int id = tid + j * 256;
        int limb = id >> 9;
        int rem = id & 511;
        int row = rem >> 3, ch = rem & 7;
        int c = cbase + row;
        const __half* srcb = limb ? g_l16 : g_h16;
        uint32_t dst = sbase + SM_B + buf * (2 * B_TILE) + limb * B_TILE + row * ROWB + ch * 16;
        cp_async16(dst, srcb + (size_t)c * 64 + ch * 8, c < segend);
    }
    CP_COMMIT();
}

__global__ void __launch_bounds__(256, 2) knn_tc_kernel() {
    extern __shared__ char smem[];
    uint32_t sbase = smem_u32(smem);
    int tid = threadIdx.x, warp = tid >> 5, lane = tid & 31;
    int qblk = blockIdx.x >> 3, seg = blockIdx.x & 7;
    int qbase = qblk * QTILE;
    int segbeg = seg * SEGSZ, segend = segbeg + SEGSZ;

    float*    Sp     = reinterpret_cast<float*>(smem + SM_S);       // [128][65]
    float*    sqc    = reinterpret_cast<float*>(smem + SM_SQ);      // [2][64]
    float*    myqs   = reinterpret_cast<float*>(smem + SM_MYQ);     // [128]
    float*    thresh = reinterpret_cast<float*>(smem + SM_TH);      // [128]
    uint32_t* maskb  = reinterpret_cast<uint32_t*>(smem + SM_MSK);  // [128][2]
    float*    sthr   = reinterpret_cast<float*>(smem + SM_STH);     // [128]

    // ---- stage A tile (2 limbs), zero-padded ----
    #pragma unroll
    for (int j = 0; j < 8; j++) {
        int id = tid + j * 256;                 // 2048 = 2 limb * 128 rows * 8 ch
        int limb = id >> 10;
        int rem = id & 1023;
        int row = rem >> 3, ch = rem & 7;
        int q = qbase + row;
        uint4 v = make_uint4(0u, 0u, 0u, 0u);
        if (q < Nn) {
            const __half* src = limb ? g_l16 : g_h16;
            v = *reinterpret_cast<const uint4*>(src + (size_t)q * 64 + ch * 8);
        }
        *reinterpret_cast<uint4*>(smem + SM_A + limb * A_TILE + row * ROWB + ch * 16) = v;
    }
    knn_prefetch(sbase, 0, segbeg, segend, tid);
    if (tid < 64) {
        int c = segbeg + tid;
        sqc[tid] = (c < segend) ? g_sq[c] : INFF;
    }
    if (tid < 128) {
        int q = qbase + tid;
        myqs[tid] = (q < Nn) ? g_sq[q] : 0.0f;
        thresh[tid] = INFF;
        sthr[tid] = INFF;
        maskb[2 * tid] = 0u;
        maskb[2 * tid + 1] = 0u;
    }
    __syncthreads();

    // scan-thread state (one thread per query row; tid<128 active)
    float bd[16]; int bi[16];
    #pragma unroll
    for (int t = 0; t < 16; t++) { bd[t] = INFF; bi[t] = -1; }

    int r0 = warp * 16 + (lane >> 2), r1 = r0 + 8;
    int cquad = 2 * (lane & 3);
    uint32_t arow = sbase + SM_A + (warp * 16 + (lane & 15)) * ROWB + (lane >> 4) * 16;

    for (int t = 0; t < NTILES; t++) {
        int buf = t & 1;
        if (t + 1 < NTILES) {
            knn_prefetch(sbase, (t + 1) & 1, segbeg + (t + 1) * CTILE, segend, tid);
            CP_WAIT1();
        } else {
            CP_WAIT0();
        }
        __syncthreads();   // B(t) visible; scan(t-1) done -> S/masks writable

        if (t + 1 < NTILES && tid < 64) {
            int c = segbeg + (t + 1) * CTILE + tid;
            sqc[((t + 1) & 1) * 64 + tid] = (c < segend) ? g_sq[c] : INFF;
        }
        // refresh shared-global threshold cache (staleness conservative-safe)
        if (tid < 128) {
            int q = qbase + tid;
            if (q < Nn) sthr[tid] = __int_as_float(__ldcg(&g_thri[q]));
        }

        // ---- MMA: 3-pass fp16 2-limb (hh + lh + hl); A frags reloaded per k ----
        float acc[8][4];
        #pragma unroll
        for (int nt = 0; nt < 8; nt++)
            #pragma unroll
            for (int r = 0; r < 4; r++) acc[nt][r] = 0.0f;

        uint32_t brow = (lane & 15) * ROWB + (lane >> 4) * 16;
        uint32_t bbuf = sbase + SM_B + buf * (2 * B_TILE);
        #pragma unroll
        for (int k = 0; k < 4; k++) {
            uint32_t ah[4], al[4];
            ldsm_x4(ah, arow + k * 32);
            ldsm_x4(al, arow + A_TILE + k * 32);
            #pragma unroll
            for (int p = 0; p < 4; p++) {
                uint32_t baddr = bbuf + p * 16 * ROWB + brow + k * 32;
                uint32_t bf[4];
                ldsm_x4(bf, baddr);
                mma_f16(acc[2 * p],     ah, bf[0], bf[2]);
                mma_f16(acc[2 * p + 1], ah, bf[1], bf[3]);
                mma_f16(acc[2 * p],     al, bf[0], bf[2]);
                mma_f16(acc[2 * p + 1], al, bf[1], bf[3]);
                ldsm_x4(bf, baddr + B_TILE);
                mma_f16(acc[2 * p],     ah, bf[0], bf[2]);
                mma_f16(acc[2 * p + 1], ah, bf[1], bf[3]);
            }
        }

        // ---- in-fragment eval + threshold filter (survivors -> S + mask) ----
        {
            float th0 = fminf(thresh[r0], sthr[r0]);
            float th1 = fminf(thresh[r1], sthr[r1]);
            float mq0 = myqs[r0],  mq1 = myqs[r1];
            #pragma unroll
            for (int nt = 0; nt < 8; nt++) {
                float2 sqp = *reinterpret_cast<const float2*>(&sqc[buf * 64 + nt * 8 + cquad]);
                float d00 = fmaf(acc[nt][0], -2.0f, mq0 + sqp.x);
                float d01 = fmaf(acc[nt][1], -2.0f, mq0 + sqp.y);
                float d10 = fmaf(acc[nt][2], -2.0f, mq1 + sqp.x);
                float d11 = fmaf(acc[nt][3], -2.0f, mq1 + sqp.y);
                int c0 = nt * 8 + cquad;
                int word = nt >> 2;
                uint32_t b0 = 1u << (c0 & 31);
                if (d00 < th0) { Sp[r0 * 65 + c0]     = d00; atomicOr(&maskb[r0 * 2 + word], b0); }
                if (d01 < th0) { Sp[r0 * 65 + c0 + 1] = d01; atomicOr(&maskb[r0 * 2 + word], b0 << 1); }
                if (d10 < th1) { Sp[r1 * 65 + c0]     = d10; atomicOr(&maskb[r1 * 2 + word], b0); }
                if (d11 < th1) { Sp[r1 * 65 + c0 + 1] = d11; atomicOr(&maskb[r1 * 2 + word], b0 << 1); }
            }
        }
        __syncthreads();

        // ---- sparse scan of survivors ----
        if (tid < 128) {
            uint32_t m0 = maskb[2 * tid], m1 = maskb[2 * tid + 1];
            if (m0 | m1) {
                maskb[2 * tid] = 0u;
                maskb[2 * tid + 1] = 0u;
                int cb = segbeg + t * CTILE;
                while (m0) {
                    int b = __ffs(m0) - 1; m0 &= m0 - 1;
                    float d2 = Sp[tid * 65 + b];
                    if (d2 < bd[15]) topk_insert(bd, bi, d2, cb + b);
                }
                while (m1) {
                    int b = __ffs(m1) - 1; m1 &= m1 - 1;
                    float d2 = Sp[tid * 65 + 32 + b];
                    if (d2 < bd[15]) topk_insert(bd, bi, d2, cb + 32 + b);
                }
                thresh[tid] = bd[15];
                atomicMin(&g_thri[qbase + tid], __float_as_int(fmaxf(bd[15], 0.0f)));
            }
        }
    }

    if (tid < 128 && qbase + tid < Nn) {
        int obase = ((qbase + tid) * NLISTS + seg) * Kk;
        #pragma unroll
        for (int t = 0; t < 16; t++) { g_cd[obase + t] = bd[t]; g_ci[obase + t] = bi[t]; }
    }
}

// ======= launch 5: merge 8 lists per query ==================================
__global__ void knn_merge_kernel() {
    int q = blockIdx.x * blockDim.x + threadIdx.x;
    if (q >= Nn) return;
    float bd[16]; int bi[16];
    #pragma unroll
    for (int t = 0; t < 16; t++) { bd[t] = INFF; bi[t] = -1; }
    int base = q * NLISTS * Kk;
    for (int s = 0; s < NLISTS; s++) {
        #pragma unroll
        for (int t = 0; t < 16; t++) {
            float d = g_cd[base + s * Kk + t];
            if (d < bd[15]) topk_insert(bd, bi, d, g_ci[base + s * Kk + t]);
        }
    }
    #pragma unroll
    for (int t = 0; t < 16; t++) g_nbr[q * Kk + t] = bi[t];
}

// ======= launch 6: pair MLP (layer-1 collapsed) + max over K ================
__global__ void pair_kernel(const float* __restrict__ W2b, const float* __restrict__ b2b) {
    __shared__ float sW2b[64 * 64];
    __shared__ float sb2b[64];
    __shared__ float hbuf[8][16][64];
    int tid = threadIdx.x;
    for (int i = tid; i < 64 * 64; i += 256) sW2b[i] = W2b[i];
    if (tid < 64) sb2b[tid] = b2b[tid];
    __syncthreads();

    int warp = tid >> 5, lane = tid & 31;
    int n = blockIdx.x * 8 + warp;
    int j0 = lane, j1 = lane + 32;

    float ci0 = g_c[n * 64 + j0], ci1 = g_c[n * 64 + j1];
    float di0 = g_d[n * 64 + j0], di1 = g_d[n * 64 + j1];
    #pragma unroll
    for (int k = 0; k < 16; k++) {
        int nb = g_nbr[n * 16 + k];
        hbuf[warp][k][j0] = fmaxf(ci0 + g_d[nb * 64 + j0] - di0, 0.0f);
        hbuf[warp][k][j1] = fmaxf(ci1 + g_d[nb * 64 + j1] - di1, 0.0f);
    }
    __syncwarp();

    float a0[16], a1[16];
    #pragma unroll
    for (int k = 0; k < 16; k++) { a0[k] = 0.0f; a1[k] = 0.0f; }
    #pragma unroll 4
    for (int t = 0; t < 64; t++) {
        float w0 = sW2b[t * 64 + j0], w1 = sW2b[t * 64 + j1];
        #pragma unroll
        for (int k = 0; k < 16; k++) {
            float v = hbuf[warp][k][t];
            a0[k] += v * w0;
            a1[k] += v * w1;
        }
    }
    float b0 = sb2b[j0], b1 = sb2b[j1];
    float mx0 = 0.0f, mx1 = 0.0f;
    #pragma unroll
    for (int k = 0; k < 16; k++) {
        mx0 = fmaxf(mx0, a0[k] + b0);
        mx1 = fmaxf(mx1, a1[k] + b1);
    }
    g_x2[n * 64 + j0] = mx0;
    g_x2[n * 64 + j1] = mx1;
}

// ======= launch 7: tail (composed M_r) ======================================
__global__ void tail_kernel(const float* __restrict__ Wr2, const float* __restrict__ br2,
                            float* __restrict__ out) {
    __shared__ float sM[64 * 64];
    __shared__ float sbb[64];
    __shared__ float sWr2[192];
    __shared__ float sbuf[8][64];
    int tid = threadIdx.x, warp = tid >> 5, lane = tid & 31;
    int r = blockIdx.x / 2500;
    for (int i = tid; i < 4096; i += 256) sM[i] = g_M[r * 4096 + i];
    if (tid < 64) sbb[tid] = g_bb[r * 64 + tid];
    if (tid < 192) sWr2[tid] = Wr2[tid];
    __syncthreads();

    int l = blockIdx.x * 8 + warp;
    int i = l - r * Nn;
    int j0 = lane, j1 = lane + 32;
    float xa = g_x2[i * 64 + j0];
    float xb = g_x2[i * 64 + j1];

    float h0 = sbb[j0], h1 = sbb[j1];
    #pragma unroll 8
    for (int t = 0; t < 32; t++) {
        float xv = __shfl_sync(0xFFFFFFFFu, xa, t);
        h0 += xv * sM[t * 64 + j0];
        h1 += xv * sM[t * 64 + j1];
    }
    #pragma unroll 8
    for (int t = 0; t < 32; t++) {
        float xv = __shfl_sync(0xFFFFFFFFu, xb, t);
        h0 += xv * sM[(32 + t) * 64 + j0];
        h1 += xv * sM[(32 + t) * 64 + j1];
    }
    h0 = fmaxf(h0, 0.0f);
    h1 = fmaxf(h1, 0.0f);
    sbuf[warp][j0] = h0;
    sbuf[warp][j1] = h1;
    __syncwarp();

    if (lane < 3) {
        float o = br2[lane];
        #pragma unroll 16
        for (int k = 0; k < 64; k++) o += sbuf[warp][k] * sWr2[k * 3 + lane];
        out[l * 3 + lane] = o;
    }
}

// ---------------- launch ----------------------------------------------------
extern "C" void kernel_launch(void* const* d_in, const int* in_sizes, int n_in,
                              void* d_out, int out_size) {
    const float* dep  = (const float*)d_in[0];
    const float* W1a  = (const float*)d_in[1];
    const float* b1a  = (const float*)d_in[2];
    const float* W1b  = (const float*)d_in[3];
    const float* b1b  = (const float*)d_in[4];
    const float* W2a  = (const float*)d_in[5];
    const float* b2a  = (const float*)d_in[6];
    const float* W2b  = (const float*)d_in[7];
    const float* b2b  = (const float*)d_in[8];
    const float* We   = (const float*)d_in[9];
    const float* be   = (const float*)d_in[10];
    const float* Wp   = (const float*)d_in[11];
    const float* bp   = (const float*)d_in[12];
    const float* Wr1  = (const float*)d_in[13];
    const float* br1  = (const float*)d_in[14];
    const float* Wr2  = (const float*)d_in[15];
    const float* br2  = (const float*)d_in[16];
    const int*   eidx = (const int*)d_in[17];
    float* out = (float*)d_out;
    (void)in_sizes; (void)n_in; (void)out_size;

    cudaFuncSetAttribute(knn_tc_kernel, cudaFuncAttributeMaxDynamicSharedMemorySize, SM_TOT);

    pre_kernel<<<7504, 256>>>(dep, W1a, b1a, We, be, Wp, bp, Wr1, br1);
    edge_kernel<<<Ee / 64, 256>>>(eidx, W1b, b1b);
    sqcvt_kernel<<<Nn / 8, 256>>>(W2a, b2a);
    knn_tc_kernel<<<NQBLK * SEGS, 256, SM_TOT>>>();
    knn_merge_kernel<<<(Nn + 255) / 256, 256>>>();
    pair_kernel<<<Nn / 8, 256>>>(W2b, b2b);
    tail_kernel<<<NOUT / 8, 256>>>(Wr2, br2, out);
}